// round 2
// baseline (speedup 1.0000x reference)
#include <cuda_runtime.h>
#include <math.h>

#define NN 16384
#define NG 256
#define KK 50
#define NB 5
#define MAXC 512     // max nodes per graph supported (binomial mean 64, sd 8 -> huge margin)
#define WARPS 8
#define SPLIT 4
#define BIGD 1e10f

// Output layout (float32, out_size = 8*N*K):
//   [0,      nK)  : edge_index row 0 (src)
//   [nK,    2nK)  : edge_index row 1 (dst)
//   [2nK,   3nK)  : dist
//   [3nK,   8nK)  : rdf [nK,5] row-major
__global__ __launch_bounds__(256) void knn_rdf_kernel(
    const float* __restrict__ pos,
    const int*   __restrict__ batch_w,   // raw words of batch (int32 or int64 layout)
    float*       __restrict__ out)
{
    __shared__ float px[MAXC], py[MAXC], pz[MAXC], sqv[MAXC];
    __shared__ float d2s[WARPS][MAXC];
    __shared__ int   slotIdx[WARPS][KK];
    __shared__ float slotD2[WARPS][KK];
    __shared__ int   sRange[2];

    const int g   = blockIdx.x;
    const int tid = threadIdx.x;

    if (tid < 2) {
        // dtype detection: int64 layout has high word 0 at odd word index NN-1
        const bool is64 = (batch_w[NN - 1] == 0);
        const int target = g + tid;            // lower_bound(batch, g) and (batch, g+1)
        int lo = 0, hi = NN;
        while (lo < hi) {
            int mid = (lo + hi) >> 1;
            int bv = is64 ? batch_w[2 * mid] : batch_w[mid];
            if (bv < target) lo = mid + 1; else hi = mid;
        }
        sRange[tid] = lo;
    }
    __syncthreads();
    const int start = sRange[0];
    const int end   = sRange[1];
    int cnt = end - start;
    if (cnt <= 0) return;
    if (cnt > MAXC) cnt = MAXC;   // safety clamp (never expected)

    // stage this graph's positions + squared norms
    for (int j = tid; j < cnt; j += blockDim.x) {
        float x = pos[3 * (start + j) + 0];
        float y = pos[3 * (start + j) + 1];
        float z = pos[3 * (start + j) + 2];
        px[j] = x; py[j] = y; pz[j] = z;
        sqv[j] = x * x + y * y + z * z;
    }
    __syncthreads();

    const int warp = tid >> 5, lane = tid & 31;
    const long long nK = (long long)NN * KK;
    const float gamma = 0.08f;                 // 1/(2*2.5^2)
    // C_b = exp(-0.5*b^2)
    const float C1 = 0.60653065971263342360f;
    const float C2 = 0.13533528323661270231f;
    const float C3 = 0.01110899653824230650f;
    const float C4 = 3.35462627902511838821e-4f;
    const float padDist = sqrtf(BIGD);         // matches sqrt(1e10) in f32 rn

    for (int i = warp + WARPS * blockIdx.y; i < cnt; i += WARPS * SPLIT) {
        const float xi = px[i], yi = py[i], zi = pz[i], si = sqv[i];

        // squared distances to all same-graph nodes (self -> BIG, matches reference mask)
        for (int j = lane; j < cnt; j += 32) {
            float d2 = si + sqv[j] - 2.0f * (xi * px[j] + yi * py[j] + zi * pz[j]);
            d2s[warp][j] = (j == i) ? BIGD : d2;
        }
        __syncwarp();

        // rank selection: rank = #{k : (d2_k, k) < (d2_j, j)}  (matches lax.top_k tie-break)
        for (int j = lane; j < cnt; j += 32) {
            if (j == i) continue;
            const float dj = d2s[warp][j];
            int rank = 0;
            #pragma unroll 4
            for (int k = 0; k < cnt; ++k) {
                float dk = d2s[warp][k];            // same addr across lanes -> smem broadcast
                rank += (dk < dj) || (dk == dj && k < j);
            }
            if (rank < KK) { slotIdx[warp][rank] = start + j; slotD2[warp][rank] = dj; }
        }
        __syncwarp();

        // output phase: coalesced lane-strided writes over the K slots
        const int v = min(cnt - 1, KK);        // number of valid (non-padding) slots
        const int ig = start + i;
        const long long eb = (long long)ig * KK;
        for (int s = lane; s < KK; s += 32) {
            float fsrc, dist, r0, r1, r2, r3, r4;
            if (s < v) {
                fsrc = (float)slotIdx[warp][s];
                dist = sqrtf(fmaxf(slotD2[warp][s], 1e-12f));
                // exp(-g(d-cb)^2) = A * t^b * Cb ; A = e^{-g d^2}, t = e^{0.4 d}
                float A = __expf(-gamma * dist * dist);
                float t = __expf(0.4f * dist);
                r0 = A;
                float p = A * t; r1 = p * C1;
                p *= t;          r2 = p * C2;
                p *= t;          r3 = p * C3;
                p *= t;          r4 = p * C4;
            } else {
                // padding: (s-v)-th masked index in ascending order over
                // {0..start-1} ∪ {ig} ∪ {end..}
                int m = s - v;
                int pidx = (m < start) ? m : ((m == start) ? ig : end + (m - start - 1));
                fsrc = (float)pidx;
                dist = padDist;
                r0 = r1 = r2 = r3 = r4 = 0.0f;
            }
            const long long e = eb + s;
            out[e]            = fsrc;          // src
            out[nK + e]       = (float)ig;     // dst
            out[2 * nK + e]   = dist;          // distance
            float* rp = out + 3 * nK + 5 * e;  // rdf bins
            rp[0] = r0; rp[1] = r1; rp[2] = r2; rp[3] = r3; rp[4] = r4;
        }
        __syncwarp();
    }
}

extern "C" void kernel_launch(void* const* d_in, const int* in_sizes, int n_in,
                              void* d_out, int out_size)
{
    const float* pos    = (const float*)d_in[0];
    const int*   batchw = (const int*)d_in[1];
    float*       out    = (float*)d_out;
    dim3 grid(NG, SPLIT);
    knn_rdf_kernel<<<grid, 256>>>(pos, batchw, out);
}

// round 3
// speedup vs baseline: 1.2608x; 1.2608x over previous
#include <cuda_runtime.h>
#include <math.h>

#define NN 16384
#define NG 256
#define KK 50
#define NB 5
#define MAXC 192     // max nodes per graph (binomial mean 64, sd 8 -> astronomically safe)
#define WARPS 8
#define SPLIT 4
#define BIGD 1e10f

// Output layout (float32, out_size = 8*N*K):
//   [0,      nK)  : edge_index row 0 (src)
//   [nK,    2nK)  : edge_index row 1 (dst)
//   [2nK,   3nK)  : dist
//   [3nK,   8nK)  : rdf [nK,5] row-major
__global__ __launch_bounds__(256) void knn_rdf_kernel(
    const float* __restrict__ pos,
    const int*   __restrict__ batch_w,   // raw words of batch (int32 or int64 layout)
    float*       __restrict__ out)
{
    __shared__ float px[MAXC], py[MAXC], pz[MAXC], sqv[MAXC];
    __shared__ unsigned long long keys[WARPS][MAXC];
    __shared__ unsigned long long slotKey[WARPS][KK];
    __shared__ int sRange[2];

    const int g   = blockIdx.x;
    const int tid = threadIdx.x;

    if (tid < 2) {
        // dtype detection: int64 layout has high word 0 at odd word index NN-1
        const bool is64 = (batch_w[NN - 1] == 0);
        const int target = g + tid;            // lower_bound(batch, g) / (batch, g+1)
        int lo = 0, hi = NN;
        while (lo < hi) {
            int mid = (lo + hi) >> 1;
            int bv = is64 ? batch_w[2 * mid] : batch_w[mid];
            if (bv < target) lo = mid + 1; else hi = mid;
        }
        sRange[tid] = lo;
    }
    __syncthreads();
    const int start = sRange[0];
    const int end   = sRange[1];
    int cnt = end - start;
    if (cnt <= 0) return;
    if (cnt > MAXC) cnt = MAXC;   // safety clamp (never expected)

    // stage this graph's positions + squared norms
    for (int j = tid; j < cnt; j += blockDim.x) {
        float x = pos[3 * (start + j) + 0];
        float y = pos[3 * (start + j) + 1];
        float z = pos[3 * (start + j) + 2];
        px[j] = x; py[j] = y; pz[j] = z;
        sqv[j] = x * x + y * y + z * z;
    }
    __syncthreads();

    const int warp = tid >> 5, lane = tid & 31;
    const long long nK = (long long)NN * KK;
    const float gamma = 0.08f;                 // 1/(2*2.5^2)
    // C_b = exp(-0.5*b^2)
    const float C1 = 0.60653065971263342360f;
    const float C2 = 0.13533528323661270231f;
    const float C3 = 0.01110899653824230650f;
    const float C4 = 3.35462627902511838821e-4f;
    const float padDist = sqrtf(BIGD);

    unsigned long long* kw = keys[warp];

    for (int i = warp + WARPS * blockIdx.y; i < cnt; i += WARPS * SPLIT) {
        const float xi = px[i], yi = py[i], zi = pz[i], si = sqv[i];

        // build sortable keys: (monotonic-mapped d2 << 14) | j — exact lax.top_k order
        for (int j = lane; j < cnt; j += 32) {
            float d2 = si + sqv[j] - 2.0f * (xi * px[j] + yi * py[j] + zi * pz[j]);
            unsigned ub = __float_as_uint(d2);
            ub ^= ((unsigned)((int)ub >> 31)) | 0x80000000u;
            unsigned long long key = ((unsigned long long)ub << 14) | (unsigned)j;
            if (j == i) key = ~0ULL;           // self never selected among reals
            kw[j] = key;
        }
        __syncwarp();

        // rank via counting, 2 candidates per lane per k-sweep
        for (int jb = 0; jb < cnt; jb += 64) {
            const int j0 = jb + lane;
            const int j1 = jb + lane + 32;
            const unsigned long long k0 = (j0 < cnt) ? kw[j0] : ~0ULL;
            const unsigned long long k1 = (j1 < cnt) ? kw[j1] : ~0ULL;
            int r0 = 0, r1 = 0;
            #pragma unroll 8
            for (int k = 0; k < cnt; ++k) {
                const unsigned long long kk = kw[k];   // broadcast LDS.64
                r0 += (kk < k0);
                r1 += (kk < k1);
            }
            if (j0 < cnt && j0 != i && r0 < KK) slotKey[warp][r0] = k0;
            if (j1 < cnt && j1 != i && r1 < KK) slotKey[warp][r1] = k1;
        }
        __syncwarp();

        // output phase: coalesced lane-strided writes over the K slots
        const int v = min(cnt - 1, KK);        // number of valid (non-padding) slots
        const int ig = start + i;
        const long long eb = (long long)ig * KK;
        for (int s = lane; s < KK; s += 32) {
            float fsrc, dist, r0, r1, r2, r3, r4;
            if (s < v) {
                const unsigned long long key = slotKey[warp][s];
                const int jloc = (int)(key & 0x3FFFULL);
                unsigned ub = (unsigned)(key >> 14);
                unsigned bits = (ub & 0x80000000u) ? (ub ^ 0x80000000u) : ~ub;
                const float d2 = __uint_as_float(bits);
                fsrc = (float)(start + jloc);
                dist = sqrtf(fmaxf(d2, 1e-12f));
                // exp(-g(d-cb)^2) = A * t^b * Cb ; A = e^{-g d^2}, t = e^{0.4 d}
                float A = __expf(-gamma * dist * dist);
                float t = __expf(0.4f * dist);
                r0 = A;
                float p = A * t; r1 = p * C1;
                p *= t;          r2 = p * C2;
                p *= t;          r3 = p * C3;
                p *= t;          r4 = p * C4;
            } else {
                // padding: (s-v)-th masked index ascending over {0..start-1} ∪ {ig} ∪ {end..}
                int m = s - v;
                int pidx = (m < start) ? m : ((m == start) ? ig : end + (m - start - 1));
                fsrc = (float)pidx;
                dist = padDist;
                r0 = r1 = r2 = r3 = r4 = 0.0f;
            }
            const long long e = eb + s;
            out[e]            = fsrc;          // src
            out[nK + e]       = (float)ig;     // dst
            out[2 * nK + e]   = dist;          // distance
            float* rp = out + 3 * nK + 5 * e;  // rdf bins
            rp[0] = r0; rp[1] = r1; rp[2] = r2; rp[3] = r3; rp[4] = r4;
        }
        __syncwarp();
    }
}

extern "C" void kernel_launch(void* const* d_in, const int* in_sizes, int n_in,
                              void* d_out, int out_size)
{
    const float* pos    = (const float*)d_in[0];
    const int*   batchw = (const int*)d_in[1];
    float*       out    = (float*)d_out;
    dim3 grid(NG, SPLIT);
    knn_rdf_kernel<<<grid, 256>>>(pos, batchw, out);
}

// round 4
// speedup vs baseline: 1.5772x; 1.2510x over previous
#include <cuda_runtime.h>
#include <math.h>

#define NN 16384
#define NG 256
#define KK 50
#define NB 5
#define MAXC 192     // max nodes per graph (mean 64, sd 8 -> astronomically safe); must be < 256
#define WARPS 8
#define SPLIT 8
#define BIGD 1e10f

// Output layout (float32, out_size = 8*N*K):
//   [0,      nK)  : edge_index row 0 (src)
//   [nK,    2nK)  : edge_index row 1 (dst)
//   [2nK,   3nK)  : dist
//   [3nK,   8nK)  : rdf [nK,5] row-major
__global__ __launch_bounds__(256) void knn_rdf_kernel(
    const float* __restrict__ pos,
    const int*   __restrict__ batch_w,   // raw words of batch (int32 or int64 layout)
    float*       __restrict__ out)
{
    __shared__ float px[MAXC], py[MAXC], pz[MAXC], sqv[MAXC];
    __shared__ __align__(16) unsigned keys[WARPS][MAXC];
    __shared__ int   slotJ[WARPS][KK];
    __shared__ float sRdf[WARPS][KK * NB];
    __shared__ int   sRange[2];

    const int g   = blockIdx.x;
    const int tid = threadIdx.x;

    if (tid < 2) {
        // dtype detection: int64 layout has high word 0 at odd word index NN-1
        const bool is64 = (batch_w[NN - 1] == 0);
        const int target = g + tid;            // lower_bound(batch, g) / (batch, g+1)
        int lo = 0, hi = NN;
        while (lo < hi) {
            int mid = (lo + hi) >> 1;
            int bv = is64 ? batch_w[2 * mid] : batch_w[mid];
            if (bv < target) lo = mid + 1; else hi = mid;
        }
        sRange[tid] = lo;
    }
    __syncthreads();
    const int start = sRange[0];
    const int end   = sRange[1];
    int cnt = end - start;
    if (cnt <= 0) return;
    if (cnt > MAXC) cnt = MAXC;   // safety clamp (never expected)
    const int cntR = (cnt + 3) & ~3;           // keys padded to multiple of 4 for LDS.128

    // stage this graph's positions + squared norms
    for (int j = tid; j < cnt; j += blockDim.x) {
        float x = pos[3 * (start + j) + 0];
        float y = pos[3 * (start + j) + 1];
        float z = pos[3 * (start + j) + 2];
        px[j] = x; py[j] = y; pz[j] = z;
        sqv[j] = x * x + y * y + z * z;
    }
    __syncthreads();

    const int warp = tid >> 5, lane = tid & 31;
    const long long nK = (long long)NN * KK;
    const float gamma = 0.08f;                 // 1/(2*2.5^2)
    // C_b = exp(-0.5*b^2)
    const float C1 = 0.60653065971263342360f;
    const float C2 = 0.13533528323661270231f;
    const float C3 = 0.01110899653824230650f;
    const float C4 = 3.35462627902511838821e-4f;
    const float padDist = sqrtf(BIGD);

    unsigned* kw = keys[warp];

    for (int i = warp + WARPS * blockIdx.y; i < cnt; i += WARPS * SPLIT) {
        const float xi = px[i], yi = py[i], zi = pz[i], si = sqv[i];

        // build 32-bit sortable keys: top-24 ordered bits of d2 | local index
        for (int j = lane; j < cntR; j += 32) {
            unsigned key = 0xFFFFFFFFu;        // pads and self: max key, never counted
            if (j < cnt && j != i) {
                float d2 = si + sqv[j] - 2.0f * (xi * px[j] + yi * py[j] + zi * pz[j]);
                unsigned ub = __float_as_uint(d2);
                ub ^= ((unsigned)((int)ub >> 31)) | 0x80000000u;   // monotonic float->uint
                key = (ub & 0xFFFFFF00u) | (unsigned)j;
            }
            kw[j] = key;
        }
        __syncwarp();

        // rank via counting; 4 candidates per lane, LDS.128 broadcast of 4 keys
        for (int jb = 0; jb < cnt; jb += 128) {
            const int j0 = jb + lane, j1 = j0 + 32, j2 = j0 + 64, j3 = j0 + 96;
            const unsigned k0 = (j0 < cnt) ? kw[j0] : 0xFFFFFFFFu;
            const unsigned k1 = (j1 < cnt) ? kw[j1] : 0xFFFFFFFFu;
            const unsigned k2 = (j2 < cnt) ? kw[j2] : 0xFFFFFFFFu;
            const unsigned k3 = (j3 < cnt) ? kw[j3] : 0xFFFFFFFFu;
            int r0 = 0, r1 = 0, r2 = 0, r3 = 0;
            #pragma unroll 4
            for (int kb = 0; kb < cntR; kb += 4) {
                const uint4 q = *(const uint4*)&kw[kb];   // broadcast LDS.128
                r0 += (q.x < k0) + (q.y < k0) + (q.z < k0) + (q.w < k0);
                r1 += (q.x < k1) + (q.y < k1) + (q.z < k1) + (q.w < k1);
                r2 += (q.x < k2) + (q.y < k2) + (q.z < k2) + (q.w < k2);
                r3 += (q.x < k3) + (q.y < k3) + (q.z < k3) + (q.w < k3);
            }
            if (j0 < cnt && j0 != i && r0 < KK) slotJ[warp][r0] = j0;
            if (j1 < cnt && j1 != i && r1 < KK) slotJ[warp][r1] = j1;
            if (j2 < cnt && j2 != i && r2 < KK) slotJ[warp][r2] = j2;
            if (j3 < cnt && j3 != i && r3 < KK) slotJ[warp][r3] = j3;
        }
        __syncwarp();

        // output phase
        const int v = min(cnt - 1, KK);        // number of valid (non-padding) slots
        const int ig = start + i;
        const long long eb = (long long)ig * KK;
        for (int s = lane; s < KK; s += 32) {
            float fsrc, dist, r0, r1, r2, r3, r4;
            if (s < v) {
                const int j = slotJ[warp][s];
                // exact d2 recompute (bit-identical to key-build expression)
                const float d2 = si + sqv[j] - 2.0f * (xi * px[j] + yi * py[j] + zi * pz[j]);
                fsrc = (float)(start + j);
                dist = sqrtf(fmaxf(d2, 1e-12f));
                // exp(-g(d-cb)^2) = A * t^b * Cb ; A = e^{-g d^2}, t = e^{0.4 d}
                float A = __expf(-gamma * dist * dist);
                float t = __expf(0.4f * dist);
                r0 = A;
                float p = A * t; r1 = p * C1;
                p *= t;          r2 = p * C2;
                p *= t;          r3 = p * C3;
                p *= t;          r4 = p * C4;
            } else {
                // padding: (s-v)-th masked index ascending over {0..start-1} ∪ {ig} ∪ {end..}
                int m = s - v;
                int pidx = (m < start) ? m : ((m == start) ? ig : end + (m - start - 1));
                fsrc = (float)pidx;
                dist = padDist;
                r0 = r1 = r2 = r3 = r4 = 0.0f;
            }
            const long long e = eb + s;
            out[e]            = fsrc;          // src   (coalesced)
            out[nK + e]       = (float)ig;     // dst   (coalesced)
            out[2 * nK + e]   = dist;          // dist  (coalesced)
            float* rs = &sRdf[warp][s * NB];   // stage rdf in smem (stride 5 words: conflict-free)
            rs[0] = r0; rs[1] = r1; rs[2] = r2; rs[3] = r3; rs[4] = r4;
        }
        __syncwarp();
        // coalesced rdf flush: 250 contiguous floats per node
        {
            float* rdst = out + 3 * nK + 5 * eb;
            const float* rsrc = sRdf[warp];
            for (int t = lane; t < KK * NB; t += 32)
                rdst[t] = rsrc[t];
        }
        __syncwarp();
    }
}

extern "C" void kernel_launch(void* const* d_in, const int* in_sizes, int n_in,
                              void* d_out, int out_size)
{
    const float* pos    = (const float*)d_in[0];
    const int*   batchw = (const int*)d_in[1];
    float*       out    = (float*)d_out;
    dim3 grid(NG, SPLIT);
    knn_rdf_kernel<<<grid, 256>>>(pos, batchw, out);
}

// round 5
// speedup vs baseline: 1.8302x; 1.1604x over previous
#include <cuda_runtime.h>
#include <math.h>

#define NN 16384
#define NG 256
#define KK 50
#define NB 5
#define MAXC 192     // max nodes per graph (mean 64, sd 8 -> astronomically safe); must be < 256
#define WARPS 8
#define SPLIT 8
#define BIGD 1e10f

// Output layout (float32, out_size = 8*N*K):
//   [0,      nK)  : edge_index row 0 (src)
//   [nK,    2nK)  : edge_index row 1 (dst)
//   [2nK,   3nK)  : dist
//   [3nK,   8nK)  : rdf [nK,5] row-major
__global__ __launch_bounds__(256) void knn_rdf_kernel(
    const float* __restrict__ pos,
    const int*   __restrict__ batch_w,   // raw words of batch (int32 or int64 layout)
    float*       __restrict__ out)
{
    __shared__ float px[MAXC], py[MAXC], pz[MAXC], sqv[MAXC];
    __shared__ __align__(16) unsigned keys[WARPS][MAXC];
    __shared__ int slotJ[WARPS][KK];
    __shared__ int sRange[2];

    const int g   = blockIdx.x;
    const int tid = threadIdx.x;

    if (tid < 2) {
        // dtype detection: int64 layout has high word 0 at odd word index NN-1
        const bool is64 = (batch_w[NN - 1] == 0);
        const int target = g + tid;            // lower_bound(batch, g) / (batch, g+1)
        int lo = 0, hi = NN;
        while (lo < hi) {
            int mid = (lo + hi) >> 1;
            int bv = is64 ? batch_w[2 * mid] : batch_w[mid];
            if (bv < target) lo = mid + 1; else hi = mid;
        }
        sRange[tid] = lo;
    }
    __syncthreads();
    const int start = sRange[0];
    const int end   = sRange[1];
    int cnt = end - start;
    if (cnt <= 0) return;
    if (cnt > MAXC) cnt = MAXC;   // safety clamp (never expected)
    const int cntR = (cnt + 3) & ~3;           // keys padded to multiple of 4 for LDS.128

    // stage this graph's positions + squared norms
    for (int j = tid; j < cnt; j += blockDim.x) {
        float x = pos[3 * (start + j) + 0];
        float y = pos[3 * (start + j) + 1];
        float z = pos[3 * (start + j) + 2];
        px[j] = x; py[j] = y; pz[j] = z;
        sqv[j] = x * x + y * y + z * z;
    }
    __syncthreads();

    const int warp = tid >> 5, lane = tid & 31;
    const long long nK = (long long)NN * KK;
    const float gamma = 0.08f;                 // 1/(2*2.5^2)
    // C_b = exp(-0.5*b^2)
    const float C1 = 0.60653065971263342360f;
    const float C2 = 0.13533528323661270231f;
    const float C3 = 0.01110899653824230650f;
    const float C4 = 3.35462627902511838821e-4f;
    const float padDist = sqrtf(BIGD);

    unsigned* kw = keys[warp];

    for (int i = warp + WARPS * blockIdx.y; i < cnt; i += WARPS * SPLIT) {
        const float xi = px[i], yi = py[i], zi = pz[i], si = sqv[i];

        // build 32-bit sortable keys: top-24 ordered bits of d2 | local index
        for (int j = lane; j < cntR; j += 32) {
            unsigned key = 0xFFFFFFFFu;        // pads and self: max key, rank >= v, never read
            if (j < cnt && j != i) {
                float d2 = si + sqv[j] - 2.0f * (xi * px[j] + yi * py[j] + zi * pz[j]);
                unsigned ub = __float_as_uint(d2);
                ub ^= ((unsigned)((int)ub >> 31)) | 0x80000000u;   // monotonic float->uint
                key = (ub & 0xFFFFFF00u) | (unsigned)j;
            }
            kw[j] = key;
        }
        __syncwarp();

        // rank via counting; 2 candidates per lane (covers cnt<=64 in one sweep),
        // LDS.128 broadcast of 4 keys per inner step
        for (int jb = 0; jb < cnt; jb += 64) {
            const int j0 = jb + lane, j1 = j0 + 32;
            const unsigned k0 = (j0 < cntR) ? kw[j0] : 0xFFFFFFFFu;
            const unsigned k1 = (j1 < cntR) ? kw[j1] : 0xFFFFFFFFu;
            int r0 = 0, r1 = 0;
            #pragma unroll 4
            for (int kb = 0; kb < cntR; kb += 4) {
                const uint4 q = *(const uint4*)&kw[kb];   // broadcast LDS.128
                r0 += (q.x < k0) + (q.y < k0) + (q.z < k0) + (q.w < k0);
                r1 += (q.x < k1) + (q.y < k1) + (q.z < k1) + (q.w < k1);
            }
            // self/pad candidates carry key 0xFFFFFFFF -> rank >= min(cnt-1,KK);
            // any such store lands in a slot the output phase never reads.
            if (r0 < KK) slotJ[warp][r0] = j0;
            if (r1 < KK) slotJ[warp][r1] = j1;
        }
        __syncwarp();

        // output phase: coalesced src/dst/dist, direct scattered rdf stores
        const int v = min(cnt - 1, KK);        // number of valid (non-padding) slots
        const int ig = start + i;
        const long long eb = (long long)ig * KK;
        for (int s = lane; s < KK; s += 32) {
            float fsrc, dist, r0, r1, r2, r3, r4;
            if (s < v) {
                const int j = slotJ[warp][s];
                // exact d2 recompute (bit-identical to key-build expression)
                const float d2 = si + sqv[j] - 2.0f * (xi * px[j] + yi * py[j] + zi * pz[j]);
                fsrc = (float)(start + j);
                dist = sqrtf(fmaxf(d2, 1e-12f));
                // exp(-g(d-cb)^2) = A * t^b * Cb ; A = e^{-g d^2}, t = e^{0.4 d}
                float A = __expf(-gamma * dist * dist);
                float t = __expf(0.4f * dist);
                r0 = A;
                float p = A * t; r1 = p * C1;
                p *= t;          r2 = p * C2;
                p *= t;          r3 = p * C3;
                p *= t;          r4 = p * C4;
            } else {
                // padding: (s-v)-th masked index ascending over {0..start-1} ∪ {ig} ∪ {end..}
                int m = s - v;
                int pidx = (m < start) ? m : ((m == start) ? ig : end + (m - start - 1));
                fsrc = (float)pidx;
                dist = padDist;
                r0 = r1 = r2 = r3 = r4 = 0.0f;
            }
            const long long e = eb + s;
            out[e]            = fsrc;          // src   (coalesced)
            out[nK + e]       = (float)ig;     // dst   (coalesced)
            out[2 * nK + e]   = dist;          // dist  (coalesced)
            float* rp = out + 3 * nK + 5 * e;  // rdf (scattered; L1 has headroom)
            rp[0] = r0; rp[1] = r1; rp[2] = r2; rp[3] = r3; rp[4] = r4;
        }
        __syncwarp();
    }
}

extern "C" void kernel_launch(void* const* d_in, const int* in_sizes, int n_in,
                              void* d_out, int out_size)
{
    const float* pos    = (const float*)d_in[0];
    const int*   batchw = (const int*)d_in[1];
    float*       out    = (float*)d_out;
    dim3 grid(NG, SPLIT);
    knn_rdf_kernel<<<grid, 256>>>(pos, batchw, out);
}

// round 6
// speedup vs baseline: 1.9596x; 1.0707x over previous
#include <cuda_runtime.h>
#include <math.h>

#define NN 16384
#define NG 256
#define KK 50
#define NB 5
#define MAXC 192     // max nodes per graph (mean 64, sd 8 -> astronomically safe); must be < 256
#define WARPS 8
#define SPLIT 8
#define BIGD 1e10f

__device__ __forceinline__ float ex2_approx(float x) {
    float r; asm("ex2.approx.f32 %0, %1;" : "=f"(r) : "f"(x)); return r;
}
__device__ __forceinline__ float sqrt_approx(float x) {
    float r; asm("sqrt.approx.f32 %0, %1;" : "=f"(r) : "f"(x)); return r;
}

// Output layout (float32, out_size = 8*N*K):
//   [0,      nK)  : edge_index row 0 (src)
//   [nK,    2nK)  : edge_index row 1 (dst)
//   [2nK,   3nK)  : dist
//   [3nK,   8nK)  : rdf [nK,5] row-major
__global__ __launch_bounds__(256) void knn_rdf_kernel(
    const float* __restrict__ pos,
    const int*   __restrict__ batch_w,   // raw words of batch (int32 or int64 layout)
    float*       __restrict__ out)
{
    __shared__ float px[MAXC], py[MAXC], pz[MAXC], sqv[MAXC];
    __shared__ __align__(16) unsigned keys[WARPS][MAXC];
    __shared__ int slotJ[WARPS][KK];
    __shared__ int sRange[2];

    const int g   = blockIdx.x;
    const int tid = threadIdx.x;

    if (tid < 2) {
        // dtype detection: int64 layout has high word 0 at odd word index NN-1
        const bool is64 = (batch_w[NN - 1] == 0);
        const int target = g + tid;            // lower_bound(batch, g) / (batch, g+1)
        int lo = 0, hi = NN;
        while (lo < hi) {
            int mid = (lo + hi) >> 1;
            int bv = is64 ? batch_w[2 * mid] : batch_w[mid];
            if (bv < target) lo = mid + 1; else hi = mid;
        }
        sRange[tid] = lo;
    }
    __syncthreads();
    const int start = sRange[0];
    const int end   = sRange[1];
    int cnt = end - start;
    if (cnt <= 0) return;
    if (cnt > MAXC) cnt = MAXC;   // safety clamp (never expected)
    const int cntR = (cnt + 3) & ~3;           // keys padded to multiple of 4 for LDS.128

    // stage this graph's positions + squared norms
    for (int j = tid; j < cnt; j += blockDim.x) {
        float x = pos[3 * (start + j) + 0];
        float y = pos[3 * (start + j) + 1];
        float z = pos[3 * (start + j) + 2];
        px[j] = x; py[j] = y; pz[j] = z;
        sqv[j] = x * x + y * y + z * z;
    }
    __syncthreads();

    const int warp = tid >> 5, lane = tid & 31;
    const unsigned nK = (unsigned)NN * KK;     // 819200, fits 32-bit
    // exponent constants: A = 2^(-0.08*log2e * d2), t = 2^(0.4*log2e * d)
    const float EA = -0.11541560327111707f;    // -0.08 * log2(e)
    const float ET =  0.57707801635558534f;    //  0.40 * log2(e)
    // C_b = exp(-0.5*b^2)
    const float C1 = 0.60653065971263342360f;
    const float C2 = 0.13533528323661270231f;
    const float C3 = 0.01110899653824230650f;
    const float C4 = 3.35462627902511838821e-4f;
    const float padDist = sqrtf(BIGD);

    unsigned* kw = keys[warp];

    for (int i = warp + WARPS * blockIdx.y; i < cnt; i += WARPS * SPLIT) {
        const float xi = px[i], yi = py[i], zi = pz[i], si = sqv[i];

        // build 32-bit sortable keys: top-24 ordered bits of d2 | local index
        for (int j = lane; j < cntR; j += 32) {
            unsigned key = 0xFFFFFFFFu;        // pads and self: max key, rank >= v, never read
            if (j < cnt && j != i) {
                float d2 = si + sqv[j] - 2.0f * (xi * px[j] + yi * py[j] + zi * pz[j]);
                unsigned ub = __float_as_uint(d2);
                ub ^= ((unsigned)((int)ub >> 31)) | 0x80000000u;   // monotonic float->uint
                key = (ub & 0xFFFFFF00u) | (unsigned)j;
            }
            kw[j] = key;
        }
        __syncwarp();

        // sweep 1: rank candidates j in [0,64) — 2 per lane, LDS.128 key broadcast
        {
            const int j0 = lane, j1 = lane + 32;
            const unsigned k0 = (j0 < cntR) ? kw[j0] : 0xFFFFFFFFu;
            const unsigned k1 = (j1 < cntR) ? kw[j1] : 0xFFFFFFFFu;
            int r0 = 0, r1 = 0;
            #pragma unroll 4
            for (int kb = 0; kb < cntR; kb += 4) {
                const uint4 q = *(const uint4*)&kw[kb];   // broadcast LDS.128
                r0 += (q.x < k0) + (q.y < k0) + (q.z < k0) + (q.w < k0);
                r1 += (q.x < k1) + (q.y < k1) + (q.z < k1) + (q.w < k1);
            }
            // invalid candidates (self/pad) carry max key -> rank lands in an unread slot
            if (r0 < KK) slotJ[warp][r0] = j0;
            if (r1 < KK) slotJ[warp][r1] = j1;
        }
        // sweep 2 (taken only when cnt > 64): 1 candidate per lane per 32-block
        for (int jb = 64; jb < cnt; jb += 32) {
            const int j0 = jb + lane;
            const unsigned k0 = (j0 < cntR) ? kw[j0] : 0xFFFFFFFFu;
            int r0 = 0;
            #pragma unroll 4
            for (int kb = 0; kb < cntR; kb += 4) {
                const uint4 q = *(const uint4*)&kw[kb];
                r0 += (q.x < k0) + (q.y < k0) + (q.z < k0) + (q.w < k0);
            }
            if (r0 < KK) slotJ[warp][r0] = j0;
        }
        __syncwarp();

        // output phase: coalesced src/dst/dist, direct scattered rdf stores, 32-bit addrs
        const int v = min(cnt - 1, KK);        // number of valid (non-padding) slots
        const int ig = start + i;
        const unsigned eb = (unsigned)ig * KK;
        float* __restrict__ p0 = out + eb;           // src
        float* __restrict__ p1 = p0 + nK;            // dst
        float* __restrict__ p2 = p1 + nK;            // dist
        float* __restrict__ pr = out + 3u * nK + 5u * eb;  // rdf base for this node
        const float figf = (float)ig;
        for (int s = lane; s < KK; s += 32) {
            float fsrc, dist, r0, r1, r2, r3, r4;
            if (s < v) {
                const int j = slotJ[warp][s];
                // exact d2 recompute (bit-identical to key-build expression)
                const float d2 = si + sqv[j] - 2.0f * (xi * px[j] + yi * py[j] + zi * pz[j]);
                fsrc = (float)(start + j);
                dist = sqrt_approx(fmaxf(d2, 1e-12f));
                // exp(-g(d-cb)^2) = A * t^b * Cb ; A = 2^(EA*d2'), t = 2^(ET*d)
                float A = ex2_approx(EA * dist * dist);
                float t = ex2_approx(ET * dist);
                r0 = A;
                float p = A * t; r1 = p * C1;
                p *= t;          r2 = p * C2;
                p *= t;          r3 = p * C3;
                p *= t;          r4 = p * C4;
            } else {
                // padding: (s-v)-th masked index ascending over {0..start-1} ∪ {ig} ∪ {end..}
                int m = s - v;
                int pidx = (m < start) ? m : ((m == start) ? ig : end + (m - start - 1));
                fsrc = (float)pidx;
                dist = padDist;
                r0 = r1 = r2 = r3 = r4 = 0.0f;
            }
            p0[s] = fsrc;
            p1[s] = figf;
            p2[s] = dist;
            float* rp = pr + 5 * s;
            rp[0] = r0; rp[1] = r1; rp[2] = r2; rp[3] = r3; rp[4] = r4;
        }
        __syncwarp();
    }
}

extern "C" void kernel_launch(void* const* d_in, const int* in_sizes, int n_in,
                              void* d_out, int out_size)
{
    const float* pos    = (const float*)d_in[0];
    const int*   batchw = (const int*)d_in[1];
    float*       out    = (float*)d_out;
    dim3 grid(NG, SPLIT);
    knn_rdf_kernel<<<grid, 256>>>(pos, batchw, out);
}

// round 7
// speedup vs baseline: 2.0182x; 1.0299x over previous
#include <cuda_runtime.h>
#include <math.h>

#define NN 16384
#define NG 256
#define KK 50
#define NB 5
#define MAXC 192     // max nodes per graph (mean 64, sd 8 -> astronomically safe); must be < 256
#define WARPS 8
#define SPLIT 8
#define BIGD 1e10f

__device__ __forceinline__ float ex2_approx(float x) {
    float r; asm("ex2.approx.f32 %0, %1;" : "=f"(r) : "f"(x)); return r;
}
__device__ __forceinline__ float sqrt_approx(float x) {
    float r; asm("sqrt.approx.f32 %0, %1;" : "=f"(r) : "f"(x)); return r;
}

// one bitonic compare-exchange layer step (cross-lane, distance d)
__device__ __forceinline__ unsigned cmpex(unsigned k, int d, bool keep_min) {
    unsigned o = __shfl_xor_sync(0xFFFFFFFFu, k, d);
    unsigned mn = min(k, o), mx = max(k, o);
    return keep_min ? mn : mx;
}

// Output layout (float32, out_size = 8*N*K):
//   [0,      nK)  : edge_index row 0 (src)
//   [nK,    2nK)  : edge_index row 1 (dst)
//   [2nK,   3nK)  : dist
//   [3nK,   8nK)  : rdf [nK,5] row-major
__global__ __launch_bounds__(256) void knn_rdf_kernel(
    const float* __restrict__ pos,
    const int*   __restrict__ batch_w,   // raw words of batch (int32 or int64 layout)
    float*       __restrict__ out)
{
    __shared__ float px[MAXC], py[MAXC], pz[MAXC], sqv[MAXC];
    __shared__ __align__(16) unsigned keys[WARPS][MAXC];  // fallback (cnt>64) only
    __shared__ int slotJ[WARPS][KK];                      // fallback only
    __shared__ int sRange[2];

    const int g   = blockIdx.x;
    const int tid = threadIdx.x;

    if (tid < 2) {
        // dtype detection: int64 layout has high word 0 at odd word index NN-1
        const bool is64 = (batch_w[NN - 1] == 0);
        const int target = g + tid;            // lower_bound(batch, g) / (batch, g+1)
        int lo = 0, hi = NN;
        while (lo < hi) {
            int mid = (lo + hi) >> 1;
            int bv = is64 ? batch_w[2 * mid] : batch_w[mid];
            if (bv < target) lo = mid + 1; else hi = mid;
        }
        sRange[tid] = lo;
    }
    __syncthreads();
    const int start = sRange[0];
    const int end   = sRange[1];
    int cnt = end - start;
    if (cnt <= 0) return;
    if (cnt > MAXC) cnt = MAXC;   // safety clamp (never expected)
    const int cntR = (cnt + 3) & ~3;

    // stage this graph's positions + squared norms
    for (int j = tid; j < cnt; j += blockDim.x) {
        float x = pos[3 * (start + j) + 0];
        float y = pos[3 * (start + j) + 1];
        float z = pos[3 * (start + j) + 2];
        px[j] = x; py[j] = y; pz[j] = z;
        sqv[j] = x * x + y * y + z * z;
    }
    __syncthreads();

    const int warp = tid >> 5, lane = tid & 31;
    const unsigned nK = (unsigned)NN * KK;     // 819200, fits 32-bit
    const float EA = -0.11541560327111707f;    // -0.08 * log2(e)
    const float ET =  0.57707801635558534f;    //  0.40 * log2(e)
    const float C1 = 0.60653065971263342360f;
    const float C2 = 0.13533528323661270231f;
    const float C3 = 0.01110899653824230650f;
    const float C4 = 3.35462627902511838821e-4f;
    const float padDist = sqrtf(BIGD);

    unsigned* kw = keys[warp];
    const int v = min(cnt - 1, KK);            // valid (non-padding) slots per node

    for (int i = warp + WARPS * blockIdx.y; i < cnt; i += WARPS * SPLIT) {
        const float xi = px[i], yi = py[i], zi = pz[i], si = sqv[i];
        const int ig = start + i;
        const unsigned eb = (unsigned)ig * KK;
        float* __restrict__ p0 = out + eb;                 // src
        float* __restrict__ p1 = p0 + nK;                  // dst
        float* __restrict__ p2 = p1 + nK;                  // dist
        float* __restrict__ pr = out + 3u * nK + 5u * eb;  // rdf base
        const float figf = (float)ig;

        // emit one slot s given the local neighbor index j (ignored when s >= v)
        auto emit = [&](int s, int j) {
            float fsrc, dist, r0, r1, r2, r3, r4;
            if (s < v) {
                const float d2 = si + sqv[j] - 2.0f * (xi * px[j] + yi * py[j] + zi * pz[j]);
                fsrc = (float)(start + j);
                dist = sqrt_approx(fmaxf(d2, 1e-12f));
                float A = ex2_approx(EA * dist * dist);
                float t = ex2_approx(ET * dist);
                r0 = A;
                float p = A * t; r1 = p * C1;
                p *= t;          r2 = p * C2;
                p *= t;          r3 = p * C3;
                p *= t;          r4 = p * C4;
            } else {
                int m = s - v;   // padding: masked indices ascending {0..start-1} ∪ {ig} ∪ {end..}
                int pidx = (m < start) ? m : ((m == start) ? ig : end + (m - start - 1));
                fsrc = (float)pidx;
                dist = padDist;
                r0 = r1 = r2 = r3 = r4 = 0.0f;
            }
            p0[s] = fsrc; p1[s] = figf; p2[s] = dist;
            float* rp = pr + 5 * s;
            rp[0] = r0; rp[1] = r1; rp[2] = r2; rp[3] = r3; rp[4] = r4;
        };

        if (cnt <= 64) {
            // ---------- fast path: register bitonic sort of 64 keys ----------
            // element e = lane + 32*r holds key; ascending sort => rank order
            auto makekey = [&](int j) -> unsigned {
                unsigned key = 0xFFFFFFFFu;
                if (j < cnt && j != i) {
                    float d2 = si + sqv[j] - 2.0f * (xi * px[j] + yi * py[j] + zi * pz[j]);
                    unsigned ub = __float_as_uint(d2);
                    ub ^= ((unsigned)((int)ub >> 31)) | 0x80000000u;
                    key = (ub & 0xFFFFFF00u) | (unsigned)j;
                }
                return key;
            };
            unsigned k0 = makekey(lane);
            unsigned k1 = makekey(lane + 32);

            // stages s=2,4,8,16: same keep_min predicate for both registers
            #pragma unroll
            for (int s = 2; s <= 16; s <<= 1) {
                #pragma unroll
                for (int d = s >> 1; d >= 1; d >>= 1) {
                    bool km = ((lane & d) == 0) == ((lane & s) == 0);
                    k0 = cmpex(k0, d, km);
                    k1 = cmpex(k1, d, km);
                }
            }
            // stage s=32: r0 ascending (up), r1 descending
            #pragma unroll
            for (int d = 16; d >= 1; d >>= 1) {
                bool pm = ((lane & d) == 0);
                k0 = cmpex(k0, d, pm);
                k1 = cmpex(k1, d, !pm);
            }
            // stage s=64: d=32 in-lane, then d=16..1 cross-lane, all ascending
            { unsigned a = min(k0, k1), b = max(k0, k1); k0 = a; k1 = b; }
            #pragma unroll
            for (int d = 16; d >= 1; d >>= 1) {
                bool pm = ((lane & d) == 0);
                k0 = cmpex(k0, d, pm);
                k1 = cmpex(k1, d, pm);
            }

            // ranks 0..31 in k0 (by lane), ranks 32..63 in k1
            emit(lane, (int)(k0 & 0xFFu));
            if (lane < KK - 32) emit(lane + 32, (int)(k1 & 0xFFu));
        } else {
            // ---------- fallback: counting rank via smem keys (proven path) ----------
            for (int j = lane; j < cntR; j += 32) {
                unsigned key = 0xFFFFFFFFu;
                if (j < cnt && j != i) {
                    float d2 = si + sqv[j] - 2.0f * (xi * px[j] + yi * py[j] + zi * pz[j]);
                    unsigned ub = __float_as_uint(d2);
                    ub ^= ((unsigned)((int)ub >> 31)) | 0x80000000u;
                    key = (ub & 0xFFFFFF00u) | (unsigned)j;
                }
                kw[j] = key;
            }
            __syncwarp();
            {
                const int j0 = lane, j1 = lane + 32;
                const unsigned k0 = kw[j0];
                const unsigned k1 = (j1 < cntR) ? kw[j1] : 0xFFFFFFFFu;
                int r0 = 0, r1 = 0;
                #pragma unroll 4
                for (int kb = 0; kb < cntR; kb += 4) {
                    const uint4 q = *(const uint4*)&kw[kb];
                    r0 += (q.x < k0) + (q.y < k0) + (q.z < k0) + (q.w < k0);
                    r1 += (q.x < k1) + (q.y < k1) + (q.z < k1) + (q.w < k1);
                }
                if (r0 < KK) slotJ[warp][r0] = j0;
                if (r1 < KK) slotJ[warp][r1] = j1;
            }
            for (int jb = 64; jb < cnt; jb += 32) {
                const int j0 = jb + lane;
                const unsigned k0 = (j0 < cntR) ? kw[j0] : 0xFFFFFFFFu;
                int r0 = 0;
                #pragma unroll 4
                for (int kb = 0; kb < cntR; kb += 4) {
                    const uint4 q = *(const uint4*)&kw[kb];
                    r0 += (q.x < k0) + (q.y < k0) + (q.z < k0) + (q.w < k0);
                }
                if (r0 < KK) slotJ[warp][r0] = j0;
            }
            __syncwarp();
            for (int s = lane; s < KK; s += 32)
                emit(s, (s < v) ? slotJ[warp][s] : 0);
            __syncwarp();
        }
    }
}

extern "C" void kernel_launch(void* const* d_in, const int* in_sizes, int n_in,
                              void* d_out, int out_size)
{
    const float* pos    = (const float*)d_in[0];
    const int*   batchw = (const int*)d_in[1];
    float*       out    = (float*)d_out;
    dim3 grid(NG, SPLIT);
    knn_rdf_kernel<<<grid, 256>>>(pos, batchw, out);
}